// round 13
// baseline (speedup 1.0000x reference)
#include <cuda_runtime.h>
#include <math.h>

// Problem constants
#define MROWS 81920          // BV*HW = 20*4096  (== B*L = 4*20480)
#define CDIM  256
#define LB    20480          // rows per batch n
#define HN    8
#define DH    32
#define NBATCH 4
#define TILES 160            // L-tiles of 128 per batch
#define TM 128
#define TK 32

// Scratch (static __device__ — no allocation allowed)
__device__ float g_xt  [MROWS * CDIM];                  // tf32(x)
__device__ float g_wt  [768 * CDIM];                    // tf32(Wqkv^T) [j][k]
__device__ float g_q   [MROWS * CDIM];                  // elu(q)+1 (fp32)
__device__ float g_qz  [MROWS * CDIM];                  // tf32(z*q)
__device__ float g_kvp [(long)640 * HN * DH * DH];      // per-tile kv partials
__device__ float g_ksp [(long)640 * HN * DH];           // per-tile k_sum partials
__device__ float g_ksum[NBATCH * CDIM];                 // [n][h*32+d]
__device__ float g_P   [NBATCH * CDIM * CDIM];          // tf32(P^T) [n][j][k]

__device__ __forceinline__ unsigned f2tf(float f) {
    unsigned u;
    asm("cvt.rna.tf32.f32 %0, %1;" : "=r"(u) : "f"(f));
    return u;
}

__device__ __forceinline__ void mma_tf32(float* c, const unsigned* a, const unsigned* b) {
    asm volatile(
        "mma.sync.aligned.m16n8k8.row.col.f32.tf32.tf32.f32 "
        "{%0,%1,%2,%3}, {%4,%5,%6,%7}, {%8,%9}, {%0,%1,%2,%3};\n"
        : "+f"(c[0]), "+f"(c[1]), "+f"(c[2]), "+f"(c[3])
        : "r"(a[0]), "r"(a[1]), "r"(a[2]), "r"(a[3]), "r"(b[0]), "r"(b[1]));
}

__device__ __forceinline__ void ldsm4(unsigned* r, unsigned addr) {
    asm volatile("ldmatrix.sync.aligned.m8n8.x4.shared.b16 {%0,%1,%2,%3}, [%4];"
        : "=r"(r[0]), "=r"(r[1]), "=r"(r[2]), "=r"(r[3]) : "r"(addr));
}

__device__ __forceinline__ void cpa16(unsigned dst, const void* src) {
    asm volatile("cp.async.cg.shared.global [%0], [%1], 16;" :: "r"(dst), "l"(src));
}
#define CP_COMMIT() asm volatile("cp.async.commit_group;")
#define CP_WAIT0()  asm volatile("cp.async.wait_group 0;")

// ---------------------------------------------------------------------------
// k_cvt: tf32-round x -> g_xt; Wqkv -> g_wt TRANSPOSED [768][256].
// ---------------------------------------------------------------------------
#define XF4 5242880L         // float4 count of x
__global__ __launch_bounds__(256) void k_cvt(const float* __restrict__ x,
                                             const float* __restrict__ W)
{
    #pragma unroll
    for (int it = 0; it < 8; ++it) {
        long i = (long)blockIdx.x * 2048 + it * 256 + threadIdx.x;
        if (i < XF4) {
            float4 v = ((const float4*)x)[i];
            uint4 u = { f2tf(v.x), f2tf(v.y), f2tf(v.z), f2tf(v.w) };
            *(uint4*)(g_xt + i * 4) = u;
        } else {
            long j = i - XF4;                  // < 49152
            int k  = (int)(j / 192);           // row of W
            int c4 = (int)(j % 192);           // float4 within row (768 cols)
            float4 v = ((const float4*)W)[j];
            int j0 = c4 * 4;
            g_wt[(j0 + 0) * CDIM + k] = __uint_as_float(f2tf(v.x));
            g_wt[(j0 + 1) * CDIM + k] = __uint_as_float(f2tf(v.y));
            g_wt[(j0 + 2) * CDIM + k] = __uint_as_float(f2tf(v.z));
            g_wt[(j0 + 3) * CDIM + k] = __uint_as_float(f2tf(v.w));
        }
    }
}

// ---------------------------------------------------------------------------
// k1: per (head, L-tile of 128 rows): qkv GEMM slice (128 x 96) via TF32 MMA,
//     cp.async double-buffered, ldmatrix fragments; elu+1; q staged->coalesced
//     STG; kv via compensated TF32 MMA; ksum. Grid (8, 640), 256 thr, occ 2.
// Smem (words): As 2x4608 @0, Bs 2x3456 @9216 (GEMM, n-major B [96][36]);
//     overlays: khi/vhi/klo/vlo 4x4224 (=16896) @0, qpl 4608 @16896,
//     sc_ks 256 @21504. Total 21760 w = 87040 B.
// ---------------------------------------------------------------------------
__device__ __forceinline__ void k1_load_async(unsigned Ab, unsigned Bb,
                                              long mbase, int h, int kb, int tid)
{
    #pragma unroll
    for (int it = 0; it < 4; ++it) {
        int idx = tid + it * 256;              // 0..1023
        int r = idx >> 3, c4 = idx & 7;
        cpa16(Ab + (r * 36 + c4 * 4) * 4, g_xt + (mbase + r) * CDIM + kb + c4 * 4);
    }
    #pragma unroll
    for (int it = 0; it < 3; ++it) {
        int idx = tid + it * 256;              // 0..767
        int r = idx >> 3, c4 = idx & 7;        // r = n_local 0..95
        int part = r >> 5, jj = r & 31;
        cpa16(Bb + (r * 36 + c4 * 4) * 4,
              g_wt + (part * 256 + h * 32 + jj) * CDIM + kb + c4 * 4);
    }
}

__global__ __launch_bounds__(256, 2) void k1_qkv()
{
    extern __shared__ float sm[];
    // Epilogue overlays (used only after final GEMM sync):
    unsigned* khi = (unsigned*)sm;                  // [32][132] (d, l)
    unsigned* vhi = khi + 4224;
    unsigned* klo = vhi + 4224;
    unsigned* vlo = klo + 4224;
    float* qpl   = sm + 16896;                      // [128][36] fp32
    float* sc_ks = sm + 21504;                      // 256 floats
    const unsigned smu = (unsigned)__cvta_generic_to_shared(sm);

    const int h    = blockIdx.x;        // 0..7
    const int tile = blockIdx.y;        // 0..639
    const int tid  = threadIdx.x;
    const int warp = tid >> 5, lane = tid & 31;
    const int wm = warp >> 1, wn = warp & 1;        // 4 x 2 warp grid
    const int rb = wm * 32, cb = wn * 48;           // warp tile 32 x 48
    const int g  = lane >> 2, tg = lane & 3;
    const long mbase = (long)tile * TM;

    // ldmatrix lane-address selectors
    const int rsel = (lane & 7) + ((lane >> 3) & 1) * 8;  // row within 16
    const int csel = (lane >> 4) * 4;                     // col 0 or 4
    unsigned aBase[2], bBase[3];
    #pragma unroll
    for (int mt = 0; mt < 2; mt++)
        aBase[mt] = smu + ((rb + mt * 16 + rsel) * 36 + csel) * 4;
    {
        const int brow = lane & 7;
        const int bntd = lane >> 4;                 // which nt of the pair
        const int bkd  = ((lane >> 3) & 1) * 4;     // k offset 0/4
        #pragma unroll
        for (int ntp = 0; ntp < 3; ntp++)
            bBase[ntp] = smu + (9216 + (cb + (ntp * 2 + bntd) * 8 + brow) * 36 + bkd) * 4;
    }

    float acc[2][6][4];
    #pragma unroll
    for (int mt = 0; mt < 2; mt++)
        #pragma unroll
        for (int nt = 0; nt < 6; nt++)
            #pragma unroll
            for (int e = 0; e < 4; e++) acc[mt][nt][e] = 0.f;

    k1_load_async(smu, smu + 9216 * 4, mbase, h, 0, tid);
    CP_COMMIT(); CP_WAIT0();
    __syncthreads();

    for (int i = 0; i < 8; i++) {
        int cur = i & 1;
        if (i < 7) {
            k1_load_async(smu + (cur ^ 1) * 4608 * 4,
                          smu + (9216 + (cur ^ 1) * 3456) * 4,
                          mbase, h, (i + 1) * TK, tid);
            CP_COMMIT();
        }
        const unsigned aOff = cur * 4608u * 4u;
        const unsigned bOff = cur * 3456u * 4u;
        #pragma unroll
        for (int ks = 0; ks < TK; ks += 8) {
            unsigned a[2][4], bb[3][4];
            ldsm4(a[0], aBase[0] + aOff + ks * 4);
            ldsm4(a[1], aBase[1] + aOff + ks * 4);
            #pragma unroll
            for (int ntp = 0; ntp < 3; ntp++)
                ldsm4(bb[ntp], bBase[ntp] + bOff + ks * 4);
            #pragma unroll
            for (int mt = 0; mt < 2; mt++)
                #pragma unroll
                for (int nt = 0; nt < 6; nt++)
                    mma_tf32(acc[mt][nt], a[mt], &bb[nt >> 1][(nt & 1) * 2]);
        }
        if (i < 7) CP_WAIT0();
        __syncthreads();
    }

    // Epilogue: elu+1 on q,k; q -> qpl plane; k,v hi/lo planes (d,l)
    #pragma unroll
    for (int mt = 0; mt < 2; mt++)
        #pragma unroll
        for (int nt = 0; nt < 6; nt++)
            #pragma unroll
            for (int e = 0; e < 4; e++) {
                int r = rb + mt * 16 + g + ((e >= 2) ? 8 : 0);
                int c = cb + nt * 8 + tg * 2 + (e & 1);
                float val = acc[mt][nt][e];
                int part = c >> 5, jj = c & 31;
                if (part == 0) {
                    val = (val > 0.f) ? (val + 1.f) : expf(val);
                    qpl[r * 36 + jj] = val;
                } else if (part == 1) {
                    val = (val > 0.f) ? (val + 1.f) : expf(val);
                    unsigned hb = f2tf(val);
                    float hf = __uint_as_float(hb);
                    khi[jj * 132 + r] = hb;
                    klo[jj * 132 + r] = f2tf(val - hf);
                } else {
                    unsigned hb = f2tf(val);
                    float hf = __uint_as_float(hb);
                    vhi[jj * 132 + r] = hb;
                    vlo[jj * 132 + r] = f2tf(val - hf);
                }
            }
    __syncthreads();

    // Coalesced q store: 128 rows x 8 float4
    #pragma unroll
    for (int it = 0; it < 4; ++it) {
        int idx = tid + it * 256;              // 0..1023
        int r = idx >> 3, c4 = idx & 7;
        float4 v = *(const float4*)&qpl[r * 36 + c4 * 4];
        *(float4*)(g_q + (mbase + r) * CDIM + h * 32 + c4 * 4) = v;
    }

    // kv[m][d] = sum_l v[l][m]*k[l][d] via compensated TF32 MMA.
    // 8 warps: warp = (mh, no); each covers m16 x d8 over all 128 l.
    {
        const int mh = warp & 1, no = warp >> 1;
        float c4v[4] = {0.f, 0.f, 0.f, 0.f};
        #pragma unroll
        for (int li = 0; li < 16; li++) {
            int l0 = li * 8;
            unsigned avh[4], avl[4], bkh[2], bkl[2];
            int ab = (mh * 16 + g) * 132 + l0 + tg;
            avh[0] = vhi[ab];            avh[1] = vhi[ab + 8 * 132];
            avh[2] = vhi[ab + 4];        avh[3] = vhi[ab + 8 * 132 + 4];
            avl[0] = vlo[ab];            avl[1] = vlo[ab + 8 * 132];
            avl[2] = vlo[ab + 4];        avl[3] = vlo[ab + 8 * 132 + 4];
            int bb = (no * 8 + g) * 132 + l0 + tg;
            bkh[0] = khi[bb];            bkh[1] = khi[bb + 4];
            bkl[0] = klo[bb];            bkl[1] = klo[bb + 4];
            mma_tf32(c4v, avh, bkh);
            mma_tf32(c4v, avh, bkl);
            mma_tf32(c4v, avl, bkh);
        }
        #pragma unroll
        for (int e = 0; e < 4; e++) {
            int m  = mh * 16 + g + ((e >= 2) ? 8 : 0);
            int d2 = no * 8 + tg * 2 + (e & 1);
            g_kvp[(long)(tile * HN + h) * 1024 + m * 32 + d2] = c4v[e];
        }

        // ksum partials: d = tid>>3 (0..31), cc = tid&7 (8 chunks of 16 l)
        {
            int d = tid >> 3, cc = tid & 7;
            float s = 0.f;
            #pragma unroll
            for (int l = cc * 16; l < cc * 16 + 16; l++)
                s += __uint_as_float(khi[d * 132 + l]) +
                     __uint_as_float(klo[d * 132 + l]);
            sc_ks[d * 8 + cc] = s;
        }
        __syncthreads();
        if (tid < 32) {
            float s2 = 0.f;
            #pragma unroll
            for (int c = 0; c < 8; c++) s2 += sc_ks[tid * 8 + c];
            g_ksp[(long)(tile * HN + h) * 32 + tid] = s2;
        }
    }
}

// ---------------------------------------------------------------------------
// k_reduceP: fixed-order reduction of kv/k_sum partials per (n,h), then
//            P^T[n][j][h*32+d] = tf32( sum_m kv[m][d] * Wp[h*32+m][j] )
// ---------------------------------------------------------------------------
__global__ __launch_bounds__(1024) void k_reduceP(const float* __restrict__ Wp)
{
    __shared__ float kvs[1024];
    const int n = blockIdx.x, h = blockIdx.y;
    const int tid = threadIdx.x;  // 0..1023 (= m*32+d)
    float s = 0.f;
    for (int t = 0; t < TILES; t++)
        s += g_kvp[((long)(n * TILES + t) * HN + h) * 1024 + tid];
    kvs[tid] = s;
    if (tid < 32) {
        float s2 = 0.f;
        for (int t = 0; t < TILES; t++)
            s2 += g_ksp[((long)(n * TILES + t) * HN + h) * 32 + tid];
        g_ksum[n * CDIM + h * 32 + tid] = s2;
    }
    __syncthreads();

    const int j  = tid & 255;
    const int d0 = (tid >> 8) * 8;
    float w[32];
    #pragma unroll
    for (int m = 0; m < 32; m++) w[m] = Wp[(h * 32 + m) * CDIM + j];
    #pragma unroll
    for (int dd = 0; dd < 8; dd++) {
        int d = d0 + dd;
        float p = 0.f;
        #pragma unroll
        for (int m = 0; m < 32; m++) p += kvs[m * 32 + d] * w[m];
        g_P[(long)n * 65536 + j * CDIM + h * 32 + d] = __uint_as_float(f2tf(p));
    }
}

// ---------------------------------------------------------------------------
// k_qz: per (row,head): z = 1/(q.ksum + eps); g_qz = tf32(z*q).
// ---------------------------------------------------------------------------
__global__ __launch_bounds__(256) void k_qz()
{
    const int row  = blockIdx.x * 8 + (threadIdx.x >> 5);
    const int lane = threadIdx.x & 31;
    const int n = row / LB;
    const float* qr = g_q + (long)row * CDIM;
    const float* ks = g_ksum + n * CDIM;
    float4 a0 = *(const float4*)(qr + lane * 8);
    float4 a1 = *(const float4*)(qr + lane * 8 + 4);
    float4 k0 = *(const float4*)(ks + lane * 8);
    float4 k1 = *(const float4*)(ks + lane * 8 + 4);
    float s = a0.x*k0.x + a0.y*k0.y + a0.z*k0.z + a0.w*k0.w
            + a1.x*k1.x + a1.y*k1.y + a1.z*k1.z + a1.w*k1.w;
    s += __shfl_xor_sync(0xffffffffu, s, 1);
    s += __shfl_xor_sync(0xffffffffu, s, 2);
    const float z = 1.f / (s + 1e-6f);
    uint4 u0 = { f2tf(a0.x*z), f2tf(a0.y*z), f2tf(a0.z*z), f2tf(a0.w*z) };
    uint4 u1 = { f2tf(a1.x*z), f2tf(a1.y*z), f2tf(a1.z*z), f2tf(a1.w*z) };
    *(uint4*)(g_qz + (long)row * CDIM + lane * 8)     = u0;
    *(uint4*)(g_qz + (long)row * CDIM + lane * 8 + 4) = u1;
}

// ---------------------------------------------------------------------------
// k3: out = qz @ P_n + b_proj via TF32 MMA, cp.async + ldmatrix.
//     Grid (640, 2), 256 threads, tile 128 x 128, warp grid 4x2 (32x64).
//     Smem: As 2x4608 @0 + Bs 2x4608 @9216 (n-major B [128][36])
//           = 18432 w = 73728 B, occ 2.
// ---------------------------------------------------------------------------
__device__ __forceinline__ void k3_load_async(unsigned Ab, unsigned Bb,
                                              const float* __restrict__ Pn,
                                              long mbase, int nblk, int kb, int tid)
{
    #pragma unroll
    for (int it = 0; it < 4; ++it) {
        int idx = tid + it * 256;              // 0..1023
        int r = idx >> 3, c4 = idx & 7;
        cpa16(Ab + (r * 36 + c4 * 4) * 4, g_qz + (mbase + r) * CDIM + kb + c4 * 4);
    }
    #pragma unroll
    for (int it = 0; it < 4; ++it) {
        int idx = tid + it * 256;              // 0..1023
        int r = idx >> 3, c4 = idx & 7;        // r = j_local 0..127
        cpa16(Bb + (r * 36 + c4 * 4) * 4,
              Pn + (nblk * 128 + r) * CDIM + kb + c4 * 4);
    }
}

__global__ __launch_bounds__(256, 2) void k3_proj(const float* __restrict__ bp,
                                                  float* __restrict__ out)
{
    extern __shared__ float sm[];
    const unsigned smu = (unsigned)__cvta_generic_to_shared(sm);

    const int tile = blockIdx.x;   // 0..639
    const int nblk = blockIdx.y;   // 0..1
    const int n    = tile / TILES;
    const float* Pn = g_P + (long)n * 65536;
    const int tid  = threadIdx.x;
    const int warp = tid >> 5, lane = tid & 31;
    const int wm = warp >> 1, wn = warp & 1;    // 4 x 2 warp grid
    const int rb = wm * 32, cb = wn * 64;       // warp tile 32 x 64
    const int g  = lane >> 2, tg = lane & 3;
    const long mbase = (long)tile * TM;

    const int rsel = (lane & 7) + ((lane >> 3) & 1) * 8;
    const int csel = (lane >> 4) * 4;
    unsigned aBase[2], bBase[4];
    #pragma unroll
    for (int mt = 0; mt < 2; mt++)
        aBase[mt] = smu + ((rb + mt * 16 + rsel) * 36 + csel) * 4;
    {
        const int brow = lane & 7;
        const int bntd = lane >> 4;
        const int bkd  = ((lane >> 3) & 1) * 4;
        #pragma unroll
        for (int ntp = 0; ntp < 4; ntp++)
            bBase[ntp] = smu + (9216 + (cb + (ntp * 2 + bntd) * 8 + brow) * 36 + bkd) * 4;
    }

    float acc[2][8][4];
    #pragma unroll
    for (int mt = 0; mt < 2; mt++)
        #pragma unroll
        for (int nt = 0; nt < 8; nt++)
            #pragma unroll
            for (int e = 0; e < 4; e++) acc[mt][nt][e] = 0.f;

    k3_load_async(smu, smu + 9216 * 4, Pn, mbase, nblk, 0, tid);
    CP_COMMIT(); CP_WAIT0();
    __syncthreads();

    for (int i = 0; i < 8; i++) {
        int cur = i & 1;
        if (i < 7) {
            k3_load_async(smu + (cur ^ 1) * 4608 * 4,
                          smu + (9216 + (cur ^ 1) * 4608) * 4,
                          Pn, mbase, nblk, (i + 1) * TK, tid);
            CP_COMMIT();
        }
        const unsigned aOff = cur * 4608u * 4u;
        const unsigned bOff = cur * 4608u * 4u;
        #pragma unroll
        for (int ks = 0; ks < TK; ks += 8) {
            unsigned a[2][4], bb[4][4];
            ldsm4(a[0], aBase[0] + aOff + ks * 4);
            ldsm4(a[1], aBase[1] + aOff + ks * 4);
            #pragma unroll
            for (int ntp = 0; ntp < 4; ntp++)
                ldsm4(bb[ntp], bBase[ntp] + bOff + ks * 4);
            #pragma unroll
            for (int mt = 0; mt < 2; mt++)
                #pragma unroll
                for (int nt = 0; nt < 8; nt++)
                    mma_tf32(acc[mt][nt], a[mt], &bb[nt >> 1][(nt & 1) * 2]);
        }
        if (i < 7) CP_WAIT0();
        __syncthreads();
    }

    #pragma unroll
    for (int mt = 0; mt < 2; mt++)
        #pragma unroll
        for (int nt = 0; nt < 8; nt++) {
            int c = cb + nt * 8 + tg * 2;
            float b0 = bp[nblk * 128 + c];
            float b1 = bp[nblk * 128 + c + 1];
            #pragma unroll
            for (int half = 0; half < 2; half++) {
                int r = rb + mt * 16 + g + half * 8;
                float2 o;
                o.x = acc[mt][nt][half * 2 + 0] + b0;
                o.y = acc[mt][nt][half * 2 + 1] + b1;
                *(float2*)(out + (mbase + r) * CDIM + nblk * 128 + c) = o;
            }
        }
}

// ---------------------------------------------------------------------------
extern "C" void kernel_launch(void* const* d_in, const int* in_sizes, int n_in,
                              void* d_out, int out_size)
{
    const float* x     = (const float*)d_in[0];
    const float* Wqkv  = (const float*)d_in[1];
    const float* Wproj = (const float*)d_in[2];
    const float* bproj = (const float*)d_in[3];
    float* out = (float*)d_out;

    cudaFuncSetAttribute(k1_qkv,  cudaFuncAttributeMaxDynamicSharedMemorySize, 21760 * 4);
    cudaFuncSetAttribute(k3_proj, cudaFuncAttributeMaxDynamicSharedMemorySize, 18432 * 4);

    k_cvt<<<2584, 256>>>(x, Wqkv);

    dim3 g1(HN, MROWS / TM);           // (8, 640)
    k1_qkv<<<g1, 256, 21760 * 4>>>();

    dim3 g2(NBATCH, HN);               // (4, 8)
    k_reduceP<<<g2, 1024>>>(Wproj);

    k_qz<<<MROWS / 8, 256>>>();

    dim3 g3(MROWS / TM, 2);            // (640, 2)
    k3_proj<<<g3, 256, 18432 * 4>>>(bproj, out);
}

// round 14
// speedup vs baseline: 1.0151x; 1.0151x over previous
#include <cuda_runtime.h>
#include <math.h>

// Problem constants
#define MROWS 81920          // BV*HW = 20*4096  (== B*L = 4*20480)
#define CDIM  256
#define LB    20480          // rows per batch n
#define HN    8
#define DH    32
#define NBATCH 4
#define TILES 160            // L-tiles of 128 per batch
#define TM 128
#define TK 32

// Scratch (static __device__ — no allocation allowed)
__device__ float g_xt  [MROWS * CDIM];                  // tf32(x)
__device__ float g_wt  [768 * CDIM];                    // tf32(Wqkv^T) [j][k]
__device__ float g_q   [MROWS * CDIM];                  // elu(q)+1 (fp32)
__device__ float g_qz  [MROWS * CDIM];                  // tf32(z*q)
__device__ float g_kvp [(long)640 * HN * DH * DH];      // per-tile kv partials
__device__ float g_ksp [(long)640 * HN * DH];           // per-tile k_sum partials
__device__ float g_ksum[NBATCH * CDIM];                 // [n][h*32+d]
__device__ float g_P   [NBATCH * CDIM * CDIM];          // tf32(P^T) [n][j][k]

__device__ __forceinline__ unsigned f2tf(float f) {
    unsigned u;
    asm("cvt.rna.tf32.f32 %0, %1;" : "=r"(u) : "f"(f));
    return u;
}

__device__ __forceinline__ void mma_tf32(float* c, const unsigned* a, const unsigned* b) {
    asm volatile(
        "mma.sync.aligned.m16n8k8.row.col.f32.tf32.tf32.f32 "
        "{%0,%1,%2,%3}, {%4,%5,%6,%7}, {%8,%9}, {%0,%1,%2,%3};\n"
        : "+f"(c[0]), "+f"(c[1]), "+f"(c[2]), "+f"(c[3])
        : "r"(a[0]), "r"(a[1]), "r"(a[2]), "r"(a[3]), "r"(b[0]), "r"(b[1]));
}

__device__ __forceinline__ void ldsm4(unsigned* r, unsigned addr) {
    asm volatile("ldmatrix.sync.aligned.m8n8.x4.shared.b16 {%0,%1,%2,%3}, [%4];"
        : "=r"(r[0]), "=r"(r[1]), "=r"(r[2]), "=r"(r[3]) : "r"(addr));
}

__device__ __forceinline__ void cpa16(unsigned dst, const void* src) {
    asm volatile("cp.async.cg.shared.global [%0], [%1], 16;" :: "r"(dst), "l"(src));
}
#define CP_COMMIT() asm volatile("cp.async.commit_group;")
#define CP_WAIT0()  asm volatile("cp.async.wait_group 0;")
#define CP_WAIT1()  asm volatile("cp.async.wait_group 1;")

// ---------------------------------------------------------------------------
// k_cvt: tf32-round x -> g_xt; Wqkv -> g_wt TRANSPOSED [768][256].
// ---------------------------------------------------------------------------
#define XF4 5242880L         // float4 count of x
__global__ __launch_bounds__(256) void k_cvt(const float* __restrict__ x,
                                             const float* __restrict__ W)
{
    #pragma unroll
    for (int it = 0; it < 8; ++it) {
        long i = (long)blockIdx.x * 2048 + it * 256 + threadIdx.x;
        if (i < XF4) {
            float4 v = ((const float4*)x)[i];
            uint4 u = { f2tf(v.x), f2tf(v.y), f2tf(v.z), f2tf(v.w) };
            *(uint4*)(g_xt + i * 4) = u;
        } else {
            long j = i - XF4;                  // < 49152
            int k  = (int)(j / 192);           // row of W
            int c4 = (int)(j % 192);           // float4 within row (768 cols)
            float4 v = ((const float4*)W)[j];
            int j0 = c4 * 4;
            g_wt[(j0 + 0) * CDIM + k] = __uint_as_float(f2tf(v.x));
            g_wt[(j0 + 1) * CDIM + k] = __uint_as_float(f2tf(v.y));
            g_wt[(j0 + 2) * CDIM + k] = __uint_as_float(f2tf(v.z));
            g_wt[(j0 + 3) * CDIM + k] = __uint_as_float(f2tf(v.w));
        }
    }
}

// ---------------------------------------------------------------------------
// k1: per (head, L-tile of 128 rows): qkv GEMM slice (128 x 96) via TF32 MMA,
//     3-stage cp.async pipeline (wait_group 1), ldmatrix fragments; elu+1;
//     q staged->coalesced STG; kv via compensated TF32 MMA; ksum.
//     Grid (8, 640), 256 threads, occ 2.
// Smem (words): 3 stages x (A 4608 + B 3456): A @ s*4608 (0..13824),
//     B @ 13824 + s*3456 (..24192). Overlays: khi/vhi/klo/vlo 4x4224 @0,
//     qpl 4608 @16896, sc_ks 256 @21504. Alloc 24192 w = 96768 B.
// ---------------------------------------------------------------------------
#define K1_AST  18432u       // A stage bytes
#define K1_BB   55296u       // B base bytes (13824 w)
#define K1_BST  13824u       // B stage bytes (3456 w)

__device__ __forceinline__ void k1_load_async(unsigned Ab, unsigned Bb,
                                              long mbase, int h, int kb, int tid)
{
    #pragma unroll
    for (int it = 0; it < 4; ++it) {
        int idx = tid + it * 256;              // 0..1023
        int r = idx >> 3, c4 = idx & 7;
        cpa16(Ab + (r * 36 + c4 * 4) * 4, g_xt + (mbase + r) * CDIM + kb + c4 * 4);
    }
    #pragma unroll
    for (int it = 0; it < 3; ++it) {
        int idx = tid + it * 256;              // 0..767
        int r = idx >> 3, c4 = idx & 7;        // r = n_local 0..95
        int part = r >> 5, jj = r & 31;
        cpa16(Bb + (r * 36 + c4 * 4) * 4,
              g_wt + (part * 256 + h * 32 + jj) * CDIM + kb + c4 * 4);
    }
}

__global__ __launch_bounds__(256, 2) void k1_qkv()
{
    extern __shared__ float sm[];
    // Epilogue overlays (used only after final GEMM sync):
    unsigned* khi = (unsigned*)sm;                  // [32][132] (d, l)
    unsigned* vhi = khi + 4224;
    unsigned* klo = vhi + 4224;
    unsigned* vlo = klo + 4224;
    float* qpl   = sm + 16896;                      // [128][36] fp32
    float* sc_ks = sm + 21504;                      // 256 floats
    const unsigned smu = (unsigned)__cvta_generic_to_shared(sm);

    const int h    = blockIdx.x;        // 0..7
    const int tile = blockIdx.y;        // 0..639
    const int tid  = threadIdx.x;
    const int warp = tid >> 5, lane = tid & 31;
    const int wm = warp >> 1, wn = warp & 1;        // 4 x 2 warp grid
    const int rb = wm * 32, cb = wn * 48;           // warp tile 32 x 48
    const int g  = lane >> 2, tg = lane & 3;
    const long mbase = (long)tile * TM;

    // ldmatrix lane-address selectors
    const int rsel = (lane & 7) + ((lane >> 3) & 1) * 8;  // row within 16
    const int csel = (lane >> 4) * 4;                     // col 0 or 4
    unsigned aBase[2], bBase[3];
    #pragma unroll
    for (int mt = 0; mt < 2; mt++)
        aBase[mt] = smu + ((rb + mt * 16 + rsel) * 36 + csel) * 4;
    {
        const int brow = lane & 7;
        const int bntd = lane >> 4;                 // which nt of the pair
        const int bkd  = ((lane >> 3) & 1) * 4;     // k offset 0/4
        #pragma unroll
        for (int ntp = 0; ntp < 3; ntp++)
            bBase[ntp] = smu + K1_BB + ((cb + (ntp * 2 + bntd) * 8 + brow) * 36 + bkd) * 4;
    }

    float acc[2][6][4];
    #pragma unroll
    for (int mt = 0; mt < 2; mt++)
        #pragma unroll
        for (int nt = 0; nt < 6; nt++)
            #pragma unroll
            for (int e = 0; e < 4; e++) acc[mt][nt][e] = 0.f;

    // Prologue: stages 0 and 1
    k1_load_async(smu, smu + K1_BB, mbase, h, 0, tid);
    CP_COMMIT();
    k1_load_async(smu + K1_AST, smu + K1_BB + K1_BST, mbase, h, TK, tid);
    CP_COMMIT();

    int st = 0;
    for (int i = 0; i < 8; i++) {
        if (i == 7) { CP_WAIT0(); } else { CP_WAIT1(); }
        __syncthreads();
        if (i < 6) {
            int ld = st + 2; if (ld >= 3) ld -= 3;
            k1_load_async(smu + ld * K1_AST, smu + K1_BB + ld * K1_BST,
                          mbase, h, (i + 2) * TK, tid);
            CP_COMMIT();
        }
        const unsigned aOff = st * K1_AST;
        const unsigned bOff = st * K1_BST;
        #pragma unroll
        for (int ks = 0; ks < TK; ks += 8) {
            unsigned a[2][4], bb[3][4];
            ldsm4(a[0], aBase[0] + aOff + ks * 4);
            ldsm4(a[1], aBase[1] + aOff + ks * 4);
            #pragma unroll
            for (int ntp = 0; ntp < 3; ntp++)
                ldsm4(bb[ntp], bBase[ntp] + bOff + ks * 4);
            #pragma unroll
            for (int mt = 0; mt < 2; mt++)
                #pragma unroll
                for (int nt = 0; nt < 6; nt++)
                    mma_tf32(acc[mt][nt], a[mt], &bb[nt >> 1][(nt & 1) * 2]);
        }
        if (++st == 3) st = 0;
    }
    __syncthreads();   // all GEMM smem reads done before overlay writes

    // Epilogue: elu+1 on q,k; q -> qpl plane; k,v hi/lo planes (d,l)
    #pragma unroll
    for (int mt = 0; mt < 2; mt++)
        #pragma unroll
        for (int nt = 0; nt < 6; nt++)
            #pragma unroll
            for (int e = 0; e < 4; e++) {
                int r = rb + mt * 16 + g + ((e >= 2) ? 8 : 0);
                int c = cb + nt * 8 + tg * 2 + (e & 1);
                float val = acc[mt][nt][e];
                int part = c >> 5, jj = c & 31;
                if (part == 0) {
                    val = (val > 0.f) ? (val + 1.f) : expf(val);
                    qpl[r * 36 + jj] = val;
                } else if (part == 1) {
                    val = (val > 0.f) ? (val + 1.f) : expf(val);
                    unsigned hb = f2tf(val);
                    float hf = __uint_as_float(hb);
                    khi[jj * 132 + r] = hb;
                    klo[jj * 132 + r] = f2tf(val - hf);
                } else {
                    unsigned hb = f2tf(val);
                    float hf = __uint_as_float(hb);
                    vhi[jj * 132 + r] = hb;
                    vlo[jj * 132 + r] = f2tf(val - hf);
                }
            }
    __syncthreads();

    // Coalesced q store: 128 rows x 8 float4
    #pragma unroll
    for (int it = 0; it < 4; ++it) {
        int idx = tid + it * 256;              // 0..1023
        int r = idx >> 3, c4 = idx & 7;
        float4 v = *(const float4*)&qpl[r * 36 + c4 * 4];
        *(float4*)(g_q + (mbase + r) * CDIM + h * 32 + c4 * 4) = v;
    }

    // kv[m][d] = sum_l v[l][m]*k[l][d] via compensated TF32 MMA.
    // 8 warps: warp = (mh, no); each covers m16 x d8 over all 128 l.
    {
        const int mh = warp & 1, no = warp >> 1;
        float c4v[4] = {0.f, 0.f, 0.f, 0.f};
        #pragma unroll
        for (int li = 0; li < 16; li++) {
            int l0 = li * 8;
            unsigned avh[4], avl[4], bkh[2], bkl[2];
            int ab = (mh * 16 + g) * 132 + l0 + tg;
            avh[0] = vhi[ab];            avh[1] = vhi[ab + 8 * 132];
            avh[2] = vhi[ab + 4];        avh[3] = vhi[ab + 8 * 132 + 4];
            avl[0] = vlo[ab];            avl[1] = vlo[ab + 8 * 132];
            avl[2] = vlo[ab + 4];        avl[3] = vlo[ab + 8 * 132 + 4];
            int bb = (no * 8 + g) * 132 + l0 + tg;
            bkh[0] = khi[bb];            bkh[1] = khi[bb + 4];
            bkl[0] = klo[bb];            bkl[1] = klo[bb + 4];
            mma_tf32(c4v, avh, bkh);
            mma_tf32(c4v, avh, bkl);
            mma_tf32(c4v, avl, bkh);
        }
        #pragma unroll
        for (int e = 0; e < 4; e++) {
            int m  = mh * 16 + g + ((e >= 2) ? 8 : 0);
            int d2 = no * 8 + tg * 2 + (e & 1);
            g_kvp[(long)(tile * HN + h) * 1024 + m * 32 + d2] = c4v[e];
        }

        // ksum partials: d = tid>>3 (0..31), cc = tid&7 (8 chunks of 16 l)
        {
            int d = tid >> 3, cc = tid & 7;
            float s = 0.f;
            #pragma unroll
            for (int l = cc * 16; l < cc * 16 + 16; l++)
                s += __uint_as_float(khi[d * 132 + l]) +
                     __uint_as_float(klo[d * 132 + l]);
            sc_ks[d * 8 + cc] = s;
        }
        __syncthreads();
        if (tid < 32) {
            float s2 = 0.f;
            #pragma unroll
            for (int c = 0; c < 8; c++) s2 += sc_ks[tid * 8 + c];
            g_ksp[(long)(tile * HN + h) * 32 + tid] = s2;
        }
    }
}

// ---------------------------------------------------------------------------
// k_reduceP: fixed-order reduction of kv/k_sum partials per (n,h), then
//            P^T[n][j][h*32+d] = tf32( sum_m kv[m][d] * Wp[h*32+m][j] )
// ---------------------------------------------------------------------------
__global__ __launch_bounds__(1024) void k_reduceP(const float* __restrict__ Wp)
{
    __shared__ float kvs[1024];
    const int n = blockIdx.x, h = blockIdx.y;
    const int tid = threadIdx.x;  // 0..1023 (= m*32+d)
    float s = 0.f;
    for (int t = 0; t < TILES; t++)
        s += g_kvp[((long)(n * TILES + t) * HN + h) * 1024 + tid];
    kvs[tid] = s;
    if (tid < 32) {
        float s2 = 0.f;
        for (int t = 0; t < TILES; t++)
            s2 += g_ksp[((long)(n * TILES + t) * HN + h) * 32 + tid];
        g_ksum[n * CDIM + h * 32 + tid] = s2;
    }
    __syncthreads();

    const int j  = tid & 255;
    const int d0 = (tid >> 8) * 8;
    float w[32];
    #pragma unroll
    for (int m = 0; m < 32; m++) w[m] = Wp[(h * 32 + m) * CDIM + j];
    #pragma unroll
    for (int dd = 0; dd < 8; dd++) {
        int d = d0 + dd;
        float p = 0.f;
        #pragma unroll
        for (int m = 0; m < 32; m++) p += kvs[m * 32 + d] * w[m];
        g_P[(long)n * 65536 + j * CDIM + h * 32 + d] = __uint_as_float(f2tf(p));
    }
}

// ---------------------------------------------------------------------------
// k_qz: per (row,head): z = 1/(q.ksum + eps); g_qz = tf32(z*q).
// ---------------------------------------------------------------------------
__global__ __launch_bounds__(256) void k_qz()
{
    const int row  = blockIdx.x * 8 + (threadIdx.x >> 5);
    const int lane = threadIdx.x & 31;
    const int n = row / LB;
    const float* qr = g_q + (long)row * CDIM;
    const float* ks = g_ksum + n * CDIM;
    float4 a0 = *(const float4*)(qr + lane * 8);
    float4 a1 = *(const float4*)(qr + lane * 8 + 4);
    float4 k0 = *(const float4*)(ks + lane * 8);
    float4 k1 = *(const float4*)(ks + lane * 8 + 4);
    float s = a0.x*k0.x + a0.y*k0.y + a0.z*k0.z + a0.w*k0.w
            + a1.x*k1.x + a1.y*k1.y + a1.z*k1.z + a1.w*k1.w;
    s += __shfl_xor_sync(0xffffffffu, s, 1);
    s += __shfl_xor_sync(0xffffffffu, s, 2);
    const float z = 1.f / (s + 1e-6f);
    uint4 u0 = { f2tf(a0.x*z), f2tf(a0.y*z), f2tf(a0.z*z), f2tf(a0.w*z) };
    uint4 u1 = { f2tf(a1.x*z), f2tf(a1.y*z), f2tf(a1.z*z), f2tf(a1.w*z) };
    *(uint4*)(g_qz + (long)row * CDIM + lane * 8)     = u0;
    *(uint4*)(g_qz + (long)row * CDIM + lane * 8 + 4) = u1;
}

// ---------------------------------------------------------------------------
// k3: out = qz @ P_n + b_proj via TF32 MMA, 3-stage cp.async + ldmatrix.
//     Grid (640, 2), 256 threads, tile 128 x 128, warp grid 4x2 (32x64).
//     Smem: 3 x (A 4608 + B 4608): A @ s*4608, B @ 13824 + s*4608.
//           Alloc 27648 w = 110592 B, occ 2.
// ---------------------------------------------------------------------------
#define K3_AST  18432u
#define K3_BB   55296u
#define K3_BST  18432u

__device__ __forceinline__ void k3_load_async(unsigned Ab, unsigned Bb,
                                              const float* __restrict__ Pn,
                                              long mbase, int nblk, int kb, int tid)
{
    #pragma unroll
    for (int it = 0; it < 4; ++it) {
        int idx = tid + it * 256;              // 0..1023
        int r = idx >> 3, c4 = idx & 7;
        cpa16(Ab + (r * 36 + c4 * 4) * 4, g_qz + (mbase + r) * CDIM + kb + c4 * 4);
    }
    #pragma unroll
    for (int it = 0; it < 4; ++it) {
        int idx = tid + it * 256;              // 0..1023
        int r = idx >> 3, c4 = idx & 7;        // r = j_local 0..127
        cpa16(Bb + (r * 36 + c4 * 4) * 4,
              Pn + (nblk * 128 + r) * CDIM + kb + c4 * 4);
    }
}

__global__ __launch_bounds__(256, 2) void k3_proj(const float* __restrict__ bp,
                                                  float* __restrict__ out)
{
    extern __shared__ float sm[];
    const unsigned smu = (unsigned)__cvta_generic_to_shared(sm);

    const int tile = blockIdx.x;   // 0..639
    const int nblk = blockIdx.y;   // 0..1
    const int n    = tile / TILES;
    const float* Pn = g_P + (long)n * 65536;
    const int tid  = threadIdx.x;
    const int warp = tid >> 5, lane = tid & 31;
    const int wm = warp >> 1, wn = warp & 1;    // 4 x 2 warp grid
    const int rb = wm * 32, cb = wn * 64;       // warp tile 32 x 64
    const int g  = lane >> 2, tg = lane & 3;
    const long mbase = (long)tile * TM;

    const int rsel = (lane & 7) + ((lane >> 3) & 1) * 8;
    const int csel = (lane >> 4) * 4;
    unsigned aBase[2], bBase[4];
    #pragma unroll
    for (int mt = 0; mt < 2; mt++)
        aBase[mt] = smu + ((rb + mt * 16 + rsel) * 36 + csel) * 4;
    {
        const int brow = lane & 7;
        const int bntd = lane >> 4;
        const int bkd  = ((lane >> 3) & 1) * 4;
        #pragma unroll
        for (int ntp = 0; ntp < 4; ntp++)
            bBase[ntp] = smu + K3_BB + ((cb + (ntp * 2 + bntd) * 8 + brow) * 36 + bkd) * 4;
    }

    float acc[2][8][4];
    #pragma unroll
    for (int mt = 0; mt < 2; mt++)
        #pragma unroll
        for (int nt = 0; nt < 8; nt++)
            #pragma unroll
            for (int e = 0; e < 4; e++) acc[mt][nt][e] = 0.f;

    // Prologue: stages 0 and 1
    k3_load_async(smu, smu + K3_BB, Pn, mbase, nblk, 0, tid);
    CP_COMMIT();
    k3_load_async(smu + K3_AST, smu + K3_BB + K3_BST, Pn, mbase, nblk, TK, tid);
    CP_COMMIT();

    int st = 0;
    for (int i = 0; i < 8; i++) {
        if (i == 7) { CP_WAIT0(); } else { CP_WAIT1(); }
        __syncthreads();
        if (i < 6) {
            int ld = st + 2; if (ld >= 3) ld -= 3;
            k3_load_async(smu + ld * K3_AST, smu + K3_BB + ld * K3_BST,
                          Pn, mbase, nblk, (i + 2) * TK, tid);
            CP_COMMIT();
        }
        const unsigned aOff = st * K3_AST;
        const unsigned bOff = st * K3_BST;
        #pragma unroll
        for (int ks = 0; ks < TK; ks += 8) {
            unsigned a[2][4], bb[4][4];
            ldsm4(a[0], aBase[0] + aOff + ks * 4);
            ldsm4(a[1], aBase[1] + aOff + ks * 4);
            #pragma unroll
            for (int ntp = 0; ntp < 4; ntp++)
                ldsm4(bb[ntp], bBase[ntp] + bOff + ks * 4);
            #pragma unroll
            for (int mt = 0; mt < 2; mt++)
                #pragma unroll
                for (int nt = 0; nt < 8; nt++)
                    mma_tf32(acc[mt][nt], a[mt], &bb[nt >> 1][(nt & 1) * 2]);
        }
        if (++st == 3) st = 0;
    }

    #pragma unroll
    for (int mt = 0; mt < 2; mt++)
        #pragma unroll
        for (int nt = 0; nt < 8; nt++) {
            int c = cb + nt * 8 + tg * 2;
            float b0 = bp[nblk * 128 + c];
            float b1 = bp[nblk * 128 + c + 1];
            #pragma unroll
            for (int half = 0; half < 2; half++) {
                int r = rb + mt * 16 + g + half * 8;
                float2 o;
                o.x = acc[mt][nt][half * 2 + 0] + b0;
                o.y = acc[mt][nt][half * 2 + 1] + b1;
                *(float2*)(out + (mbase + r) * CDIM + nblk * 128 + c) = o;
            }
        }
}

// ---------------------------------------------------------------------------
extern "C" void kernel_launch(void* const* d_in, const int* in_sizes, int n_in,
                              void* d_out, int out_size)
{
    const float* x     = (const float*)d_in[0];
    const float* Wqkv  = (const float*)d_in[1];
    const float* Wproj = (const float*)d_in[2];
    const float* bproj = (const float*)d_in[3];
    float* out = (float*)d_out;

    cudaFuncSetAttribute(k1_qkv,  cudaFuncAttributeMaxDynamicSharedMemorySize, 96768);
    cudaFuncSetAttribute(k3_proj, cudaFuncAttributeMaxDynamicSharedMemorySize, 110592);

    k_cvt<<<2584, 256>>>(x, Wqkv);

    dim3 g1(HN, MROWS / TM);           // (8, 640)
    k1_qkv<<<g1, 256, 96768>>>();

    dim3 g2(NBATCH, HN);               // (4, 8)
    k_reduceP<<<g2, 1024>>>(Wproj);

    k_qz<<<MROWS / 8, 256>>>();

    dim3 g3(MROWS / TM, 2);            // (640, 2)
    k3_proj<<<g3, 256, 110592>>>(bproj, out);
}

// round 16
// speedup vs baseline: 1.0960x; 1.0797x over previous
#include <cuda_runtime.h>
#include <math.h>

// Problem constants
#define MROWS 81920          // BV*HW = 20*4096  (== B*L = 4*20480)
#define CDIM  256
#define LB    20480          // rows per batch n
#define HN    8
#define DH    32
#define NBATCH 4
#define TILES 160            // L-tiles of 128 per batch
#define TM 128
#define TK 32

// Scratch (static __device__ — no allocation allowed)
__device__ float g_wt  [768 * CDIM];                    // tf32(Wqkv^T) [j][k]
__device__ float g_q   [MROWS * CDIM];                  // elu(q)+1 (fp32)
__device__ float g_qz  [MROWS * CDIM];                  // tf32(z*q)
__device__ float g_kvp [(long)640 * HN * DH * DH];      // per-tile kv partials
__device__ float g_ksp [(long)640 * HN * DH];           // per-tile k_sum partials
__device__ float g_ksum[NBATCH * CDIM];                 // [n][h*32+d]
__device__ float g_P   [NBATCH * CDIM * CDIM];          // tf32(P^T) [n][j][k]

__device__ __forceinline__ unsigned f2tf(float f) {
    unsigned u;
    asm("cvt.rna.tf32.f32 %0, %1;" : "=r"(u) : "f"(f));
    return u;
}

__device__ __forceinline__ void mma_tf32(float* c, const unsigned* a, const unsigned* b) {
    asm volatile(
        "mma.sync.aligned.m16n8k8.row.col.f32.tf32.tf32.f32 "
        "{%0,%1,%2,%3}, {%4,%5,%6,%7}, {%8,%9}, {%0,%1,%2,%3};\n"
        : "+f"(c[0]), "+f"(c[1]), "+f"(c[2]), "+f"(c[3])
        : "r"(a[0]), "r"(a[1]), "r"(a[2]), "r"(a[3]), "r"(b[0]), "r"(b[1]));
}

__device__ __forceinline__ void ldsm4(unsigned* r, unsigned addr) {
    asm volatile("ldmatrix.sync.aligned.m8n8.x4.shared.b16 {%0,%1,%2,%3}, [%4];"
        : "=r"(r[0]), "=r"(r[1]), "=r"(r[2]), "=r"(r[3]) : "r"(addr));
}

__device__ __forceinline__ void cpa16(unsigned dst, const void* src) {
    asm volatile("cp.async.cg.shared.global [%0], [%1], 16;" :: "r"(dst), "l"(src));
}
#define CP_COMMIT() asm volatile("cp.async.commit_group;")
#define CP_WAIT0()  asm volatile("cp.async.wait_group 0;")
#define CP_WAIT1()  asm volatile("cp.async.wait_group 1;")

// ---------------------------------------------------------------------------
// k_cvtW: Wqkv [256][768] -> g_wt = tf32(W^T) [768][256] (RNA rounding).
// ---------------------------------------------------------------------------
__global__ __launch_bounds__(256) void k_cvtW(const float* __restrict__ W)
{
    int i0 = (blockIdx.x * 256 + threadIdx.x) * 4;   // 4 consecutive elems
    float4 v = *(const float4*)(W + i0);
    int k = i0 / 768, j = i0 % 768;                  // 768 % 4 == 0: same row
    g_wt[(j + 0) * CDIM + k] = __uint_as_float(f2tf(v.x));
    g_wt[(j + 1) * CDIM + k] = __uint_as_float(f2tf(v.y));
    g_wt[(j + 2) * CDIM + k] = __uint_as_float(f2tf(v.z));
    g_wt[(j + 3) * CDIM + k] = __uint_as_float(f2tf(v.w));
}

// ---------------------------------------------------------------------------
// k1: per (head, L-tile of 128 rows): qkv GEMM slice (128 x 96) via TF32 MMA,
//     3-stage cp.async pipeline (wait_group 1), ldmatrix fragments; elu+1;
//     q staged->coalesced STG; kv via compensated TF32 MMA; ksum.
//     A streamed RAW from x (fp32 bits truncated to tf32 by HMMA).
//     Grid (8, 640), 256 threads, occ 2.
// ---------------------------------------------------------------------------
#define K1_AST  18432u       // A stage bytes
#define K1_BB   55296u       // B base bytes (13824 w)
#define K1_BST  13824u       // B stage bytes (3456 w)

__device__ __forceinline__ void k1_load_async(const float* __restrict__ x,
                                              unsigned Ab, unsigned Bb,
                                              long mbase, int h, int kb, int tid)
{
    #pragma unroll
    for (int it = 0; it < 4; ++it) {
        int idx = tid + it * 256;              // 0..1023
        int r = idx >> 3, c4 = idx & 7;
        cpa16(Ab + (r * 36 + c4 * 4) * 4, x + (mbase + r) * CDIM + kb + c4 * 4);
    }
    #pragma unroll
    for (int it = 0; it < 3; ++it) {
        int idx = tid + it * 256;              // 0..767
        int r = idx >> 3, c4 = idx & 7;        // r = n_local 0..95
        int part = r >> 5, jj = r & 31;
        cpa16(Bb + (r * 36 + c4 * 4) * 4,
              g_wt + (part * 256 + h * 32 + jj) * CDIM + kb + c4 * 4);
    }
}

__global__ __launch_bounds__(256, 2) void k1_qkv(const float* __restrict__ x)
{
    extern __shared__ float sm[];
    unsigned* khi = (unsigned*)sm;                  // [32][132] (d, l)
    unsigned* vhi = khi + 4224;
    unsigned* klo = vhi + 4224;
    unsigned* vlo = klo + 4224;
    float* qpl   = sm + 16896;                      // [128][36] fp32
    float* sc_ks = sm + 21504;                      // 256 floats
    const unsigned smu = (unsigned)__cvta_generic_to_shared(sm);

    const int h    = blockIdx.x;        // 0..7
    const int tile = blockIdx.y;        // 0..639
    const int tid  = threadIdx.x;
    const int warp = tid >> 5, lane = tid & 31;
    const int wm = warp >> 1, wn = warp & 1;        // 4 x 2 warp grid
    const int rb = wm * 32, cb = wn * 48;           // warp tile 32 x 48
    const int g  = lane >> 2, tg = lane & 3;
    const long mbase = (long)tile * TM;

    const int rsel = (lane & 7) + ((lane >> 3) & 1) * 8;
    const int csel = (lane >> 4) * 4;
    unsigned aBase[2], bBase[3];
    #pragma unroll
    for (int mt = 0; mt < 2; mt++)
        aBase[mt] = smu + ((rb + mt * 16 + rsel) * 36 + csel) * 4;
    {
        const int brow = lane & 7;
        const int bntd = lane >> 4;
        const int bkd  = ((lane >> 3) & 1) * 4;
        #pragma unroll
        for (int ntp = 0; ntp < 3; ntp++)
            bBase[ntp] = smu + K1_BB + ((cb + (ntp * 2 + bntd) * 8 + brow) * 36 + bkd) * 4;
    }

    float acc[2][6][4];
    #pragma unroll
    for (int mt = 0; mt < 2; mt++)
        #pragma unroll
        for (int nt = 0; nt < 6; nt++)
            #pragma unroll
            for (int e = 0; e < 4; e++) acc[mt][nt][e] = 0.f;

    k1_load_async(x, smu, smu + K1_BB, mbase, h, 0, tid);
    CP_COMMIT();
    k1_load_async(x, smu + K1_AST, smu + K1_BB + K1_BST, mbase, h, TK, tid);
    CP_COMMIT();

    int st = 0;
    for (int i = 0; i < 8; i++) {
        if (i == 7) { CP_WAIT0(); } else { CP_WAIT1(); }
        __syncthreads();
        if (i < 6) {
            int ld = st + 2; if (ld >= 3) ld -= 3;
            k1_load_async(x, smu + ld * K1_AST, smu + K1_BB + ld * K1_BST,
                          mbase, h, (i + 2) * TK, tid);
            CP_COMMIT();
        }
        const unsigned aOff = st * K1_AST;
        const unsigned bOff = st * K1_BST;
        #pragma unroll
        for (int ks = 0; ks < TK; ks += 8) {
            unsigned a[2][4], bb[3][4];
            ldsm4(a[0], aBase[0] + aOff + ks * 4);
            ldsm4(a[1], aBase[1] + aOff + ks * 4);
            #pragma unroll
            for (int ntp = 0; ntp < 3; ntp++)
                ldsm4(bb[ntp], bBase[ntp] + bOff + ks * 4);
            #pragma unroll
            for (int mt = 0; mt < 2; mt++)
                #pragma unroll
                for (int nt = 0; nt < 6; nt++)
                    mma_tf32(acc[mt][nt], a[mt], &bb[nt >> 1][(nt & 1) * 2]);
        }
        if (++st == 3) st = 0;
    }
    __syncthreads();   // all GEMM smem reads done before overlay writes

    // Epilogue: elu+1 on q,k; q -> qpl plane; k,v hi/lo planes (d,l)
    #pragma unroll
    for (int mt = 0; mt < 2; mt++)
        #pragma unroll
        for (int nt = 0; nt < 6; nt++)
            #pragma unroll
            for (int e = 0; e < 4; e++) {
                int r = rb + mt * 16 + g + ((e >= 2) ? 8 : 0);
                int c = cb + nt * 8 + tg * 2 + (e & 1);
                float val = acc[mt][nt][e];
                int part = c >> 5, jj = c & 31;
                if (part == 0) {
                    val = (val > 0.f) ? (val + 1.f) : expf(val);
                    qpl[r * 36 + jj] = val;
                } else if (part == 1) {
                    val = (val > 0.f) ? (val + 1.f) : expf(val);
                    unsigned hb = f2tf(val);
                    float hf = __uint_as_float(hb);
                    khi[jj * 132 + r] = hb;
                    klo[jj * 132 + r] = f2tf(val - hf);
                } else {
                    unsigned hb = f2tf(val);
                    float hf = __uint_as_float(hb);
                    vhi[jj * 132 + r] = hb;
                    vlo[jj * 132 + r] = f2tf(val - hf);
                }
            }
    __syncthreads();

    // Coalesced q store: 128 rows x 8 float4
    #pragma unroll
    for (int it = 0; it < 4; ++it) {
        int idx = tid + it * 256;              // 0..1023
        int r = idx >> 3, c4 = idx & 7;
        float4 v = *(const float4*)&qpl[r * 36 + c4 * 4];
        *(float4*)(g_q + (mbase + r) * CDIM + h * 32 + c4 * 4) = v;
    }

    // kv[m][d] = sum_l v[l][m]*k[l][d] via compensated TF32 MMA.
    {
        const int mh = warp & 1, no = warp >> 1;
        float c4v[4] = {0.f, 0.f, 0.f, 0.f};
        #pragma unroll
        for (int li = 0; li < 16; li++) {
            int l0 = li * 8;
            unsigned avh[4], avl[4], bkh[2], bkl[2];
            int ab = (mh * 16 + g) * 132 + l0 + tg;
            avh[0] = vhi[ab];            avh[1] = vhi[ab + 8 * 132];
            avh[2] = vhi[ab + 4];        avh[3] = vhi[ab + 8 * 132 + 4];
            avl[0] = vlo[ab];            avl[1] = vlo[ab + 8 * 132];
            avl[2] = vlo[ab + 4];        avl[3] = vlo[ab + 8 * 132 + 4];
            int bb = (no * 8 + g) * 132 + l0 + tg;
            bkh[0] = khi[bb];            bkh[1] = khi[bb + 4];
            bkl[0] = klo[bb];            bkl[1] = klo[bb + 4];
            mma_tf32(c4v, avh, bkh);
            mma_tf32(c4v, avh, bkl);
            mma_tf32(c4v, avl, bkh);
        }
        #pragma unroll
        for (int e = 0; e < 4; e++) {
            int m  = mh * 16 + g + ((e >= 2) ? 8 : 0);
            int d2 = no * 8 + tg * 2 + (e & 1);
            g_kvp[(long)(tile * HN + h) * 1024 + m * 32 + d2] = c4v[e];
        }

        // ksum partials: d = tid>>3 (0..31), cc = tid&7 (8 chunks of 16 l)
        {
            int d = tid >> 3, cc = tid & 7;
            float s = 0.f;
            #pragma unroll
            for (int l = cc * 16; l < cc * 16 + 16; l++)
                s += __uint_as_float(khi[d * 132 + l]) +
                     __uint_as_float(klo[d * 132 + l]);
            sc_ks[d * 8 + cc] = s;
        }
        __syncthreads();
        if (tid < 32) {
            float s2 = 0.f;
            #pragma unroll
            for (int c = 0; c < 8; c++) s2 += sc_ks[tid * 8 + c];
            g_ksp[(long)(tile * HN + h) * 32 + tid] = s2;
        }
    }
}

// ---------------------------------------------------------------------------
// k_reduceP: fixed-order reduction of kv/k_sum partials per (n,h), then
//            P^T[n][j][h*32+d] = tf32( sum_m kv[m][d] * Wp[h*32+m][j] )
// ---------------------------------------------------------------------------
__global__ __launch_bounds__(1024) void k_reduceP(const float* __restrict__ Wp)
{
    __shared__ float kvs[1024];
    const int n = blockIdx.x, h = blockIdx.y;
    const int tid = threadIdx.x;  // 0..1023 (= m*32+d)
    float s = 0.f;
    for (int t = 0; t < TILES; t++)
        s += g_kvp[((long)(n * TILES + t) * HN + h) * 1024 + tid];
    kvs[tid] = s;
    if (tid < 32) {
        float s2 = 0.f;
        for (int t = 0; t < TILES; t++)
            s2 += g_ksp[((long)(n * TILES + t) * HN + h) * 32 + tid];
        g_ksum[n * CDIM + h * 32 + tid] = s2;
    }
    __syncthreads();

    const int j  = tid & 255;
    const int d0 = (tid >> 8) * 8;
    float w[32];
    #pragma unroll
    for (int m = 0; m < 32; m++) w[m] = Wp[(h * 32 + m) * CDIM + j];
    #pragma unroll
    for (int dd = 0; dd < 8; dd++) {
        int d = d0 + dd;
        float p = 0.f;
        #pragma unroll
        for (int m = 0; m < 32; m++) p += kvs[m * 32 + d] * w[m];
        g_P[(long)n * 65536 + j * CDIM + h * 32 + d] = __uint_as_float(f2tf(p));
    }
}

// ---------------------------------------------------------------------------
// k_qz: per (row,head): z = 1/(q.ksum + eps); g_qz = tf32(z*q).
// ---------------------------------------------------------------------------
__global__ __launch_bounds__(256) void k_qz()
{
    const int row  = blockIdx.x * 8 + (threadIdx.x >> 5);
    const int lane = threadIdx.x & 31;
    const int n = row / LB;
    const float* qr = g_q + (long)row * CDIM;
    const float* ks = g_ksum + n * CDIM;
    float4 a0 = *(const float4*)(qr + lane * 8);
    float4 a1 = *(const float4*)(qr + lane * 8 + 4);
    float4 k0 = *(const float4*)(ks + lane * 8);
    float4 k1 = *(const float4*)(ks + lane * 8 + 4);
    float s = a0.x*k0.x + a0.y*k0.y + a0.z*k0.z + a0.w*k0.w
            + a1.x*k1.x + a1.y*k1.y + a1.z*k1.z + a1.w*k1.w;
    s += __shfl_xor_sync(0xffffffffu, s, 1);
    s += __shfl_xor_sync(0xffffffffu, s, 2);
    const float z = 1.f / (s + 1e-6f);
    uint4 u0 = { f2tf(a0.x*z), f2tf(a0.y*z), f2tf(a0.z*z), f2tf(a0.w*z) };
    uint4 u1 = { f2tf(a1.x*z), f2tf(a1.y*z), f2tf(a1.z*z), f2tf(a1.w*z) };
    *(uint4*)(g_qz + (long)row * CDIM + lane * 8)     = u0;
    *(uint4*)(g_qz + (long)row * CDIM + lane * 8 + 4) = u1;
}

// ---------------------------------------------------------------------------
// k3: out = qz @ P_n + b_proj via TF32 MMA, 3-stage cp.async + ldmatrix.
//     Grid (640, 2), 256 threads, tile 128 x 128, warp grid 4x2 (32x64).
// ---------------------------------------------------------------------------
#define K3_AST  18432u
#define K3_BB   55296u
#define K3_BST  18432u

__device__ __forceinline__ void k3_load_async(unsigned Ab, unsigned Bb,
                                              const float* __restrict__ Pn,
                                              long mbase, int nblk, int kb, int tid)
{
    #pragma unroll
    for (int it = 0; it < 4; ++it) {
        int idx = tid + it * 256;              // 0..1023
        int r = idx >> 3, c4 = idx & 7;
        cpa16(Ab + (r * 36 + c4 * 4) * 4, g_qz + (mbase + r) * CDIM + kb + c4 * 4);
    }
    #pragma unroll
    for (int it = 0; it < 4; ++it) {
        int idx = tid + it * 256;              // 0..1023
        int r = idx >> 3, c4 = idx & 7;        // r = j_local 0..127
        cpa16(Bb + (r * 36 + c4 * 4) * 4,
              Pn + (nblk * 128 + r) * CDIM + kb + c4 * 4);
    }
}

__global__ __launch_bounds__(256, 2) void k3_proj(const float* __restrict__ bp,
                                                  float* __restrict__ out)
{
    extern __shared__ float sm[];
    const unsigned smu = (unsigned)__cvta_generic_to_shared(sm);

    const int tile = blockIdx.x;   // 0..639
    const int nblk = blockIdx.y;   // 0..1
    const int n    = tile / TILES;
    const float* Pn = g_P + (long)n * 65536;
    const int tid  = threadIdx.x;
    const int warp = tid >> 5, lane = tid & 31;
    const int wm = warp >> 1, wn = warp & 1;    // 4 x 2 warp grid
    const int rb = wm * 32, cb = wn * 64;       // warp tile 32 x 64
    const int g  = lane >> 2, tg = lane & 3;
    const long mbase = (long)tile * TM;

    const int rsel = (lane & 7) + ((lane >> 3) & 1) * 8;
    const int csel = (lane >> 4) * 4;
    unsigned aBase[2], bBase[4];
    #pragma unroll
    for (int mt = 0; mt < 2; mt++)
        aBase[mt] = smu + ((rb + mt * 16 + rsel) * 36 + csel) * 4;
    {
        const int brow = lane & 7;
        const int bntd = lane >> 4;
        const int bkd  = ((lane >> 3) & 1) * 4;
        #pragma unroll
        for (int ntp = 0; ntp < 4; ntp++)
            bBase[ntp] = smu + K3_BB + ((cb + (ntp * 2 + bntd) * 8 + brow) * 36 + bkd) * 4;
    }

    float acc[2][8][4];
    #pragma unroll
    for (int mt = 0; mt < 2; mt++)
        #pragma unroll
        for (int nt = 0; nt < 8; nt++)
            #pragma unroll
            for (int e = 0; e < 4; e++) acc[mt][nt][e] = 0.f;

    k3_load_async(smu, smu + K3_BB, Pn, mbase, nblk, 0, tid);
    CP_COMMIT();
    k3_load_async(smu + K3_AST, smu + K3_BB + K3_BST, Pn, mbase, nblk, TK, tid);
    CP_COMMIT();

    int st = 0;
    for (int i = 0; i < 8; i++) {
        if (i == 7) { CP_WAIT0(); } else { CP_WAIT1(); }
        __syncthreads();
        if (i < 6) {
            int ld = st + 2; if (ld >= 3) ld -= 3;
            k3_load_async(smu + ld * K3_AST, smu + K3_BB + ld * K3_BST,
                          Pn, mbase, nblk, (i + 2) * TK, tid);
            CP_COMMIT();
        }
        const unsigned aOff = st * K3_AST;
        const unsigned bOff = st * K3_BST;
        #pragma unroll
        for (int ks = 0; ks < TK; ks += 8) {
            unsigned a[2][4], bb[4][4];
            ldsm4(a[0], aBase[0] + aOff + ks * 4);
            ldsm4(a[1], aBase[1] + aOff + ks * 4);
            #pragma unroll
            for (int ntp = 0; ntp < 4; ntp++)
                ldsm4(bb[ntp], bBase[ntp] + bOff + ks * 4);
            #pragma unroll
            for (int mt = 0; mt < 2; mt++)
                #pragma unroll
                for (int nt = 0; nt < 8; nt++)
                    mma_tf32(acc[mt][nt], a[mt], &bb[nt >> 1][(nt & 1) * 2]);
        }
        if (++st == 3) st = 0;
    }

    #pragma unroll
    for (int mt = 0; mt < 2; mt++)
        #pragma unroll
        for (int nt = 0; nt < 8; nt++) {
            int c = cb + nt * 8 + tg * 2;
            float b0 = bp[nblk * 128 + c];
            float b1 = bp[nblk * 128 + c + 1];
            #pragma unroll
            for (int half = 0; half < 2; half++) {
                int r = rb + mt * 16 + g + half * 8;
                float2 o;
                o.x = acc[mt][nt][half * 2 + 0] + b0;
                o.y = acc[mt][nt][half * 2 + 1] + b1;
                *(float2*)(out + (mbase + r) * CDIM + nblk * 128 + c) = o;
            }
        }
}

// ---------------------------------------------------------------------------
extern "C" void kernel_launch(void* const* d_in, const int* in_sizes, int n_in,
                              void* d_out, int out_size)
{
    const float* x     = (const float*)d_in[0];
    const float* Wqkv  = (const float*)d_in[1];
    const float* Wproj = (const float*)d_in[2];
    const float* bproj = (const float*)d_in[3];
    float* out = (float*)d_out;

    cudaFuncSetAttribute(k1_qkv,  cudaFuncAttributeMaxDynamicSharedMemorySize, 96768);
    cudaFuncSetAttribute(k3_proj, cudaFuncAttributeMaxDynamicSharedMemorySize, 110592);

    k_cvtW<<<192, 256>>>(Wqkv);        // 196608 elems / (256*4)

    dim3 g1(HN, MROWS / TM);           // (8, 640)
    k1_qkv<<<g1, 256, 96768>>>(x);

    dim3 g2(NBATCH, HN);               // (4, 8)
    k_reduceP<<<g2, 1024>>>(Wproj);

    k_qz<<<MROWS / 8, 256>>>();

    dim3 g3(MROWS / TM, 2);            // (640, 2)
    k3_proj<<<g3, 256, 110592>>>(bproj, out);
}